// round 1
// baseline (speedup 1.0000x reference)
#include <cuda_runtime.h>
#include <math_constants.h>

#define DIM 2048
#define HID 8192
#define NTOK 8192

// Scratch (device globals: allocation-free per harness rules)
__device__ float g_wfcq[(size_t)HID * DIM];     //  64 MB quantized w_fc
__device__ float g_wprojq[(size_t)DIM * HID];   //  64 MB quantized w_proj
__device__ float g_act[(size_t)NTOK * HID];     // 256 MB relu(h)^2 intermediate

// ---------------------------------------------------------------------------
// Blockwise symmetric int5 MSE quant-dequant. One warp per 64-element block.
// Bit-exact vs the jnp reference: IEEE div, round-half-even (rintf), no FMA
// contraction in error terms, SHRINKS computed like np.linspace in double.
// ---------------------------------------------------------------------------
__global__ void quant_kernel(const float* __restrict__ w, float* __restrict__ wq, int nblk)
{
    int gw   = (int)((blockIdx.x * blockDim.x + threadIdx.x) >> 5);
    int lane = threadIdx.x & 31;
    if (gw >= nblk) return;

    size_t base = (size_t)gw * 64;
    float w0 = w[base + lane];
    float w1 = w[base + 32 + lane];

    float am = fmaxf(fabsf(w0), fabsf(w1));
    #pragma unroll
    for (int o = 16; o; o >>= 1) am = fmaxf(am, __shfl_xor_sync(0xffffffffu, am, o));

    float bs = __fdiv_rn(fmaxf(am, 1e-8f), 15.0f);   // base = max(amax,1e-8)/QMAX

    float best_err   = CUDART_INF_F;
    float best_scale = bs;

    #pragma unroll 1
    for (int i = 0; i < 16; i++) {
        // np.linspace(0.4, 1.0, 16): double arithmetic, exact endpoint
        double sd = (i == 15) ? 1.0 : (0.4 + (double)i * (0.6 / 15.0));
        float  s  = (float)sd;
        float scale = __fmul_rn(bs, s);

        float q0 = fminf(fmaxf(rintf(__fdiv_rn(w0, scale)), -15.0f), 15.0f);
        float q1 = fminf(fmaxf(rintf(__fdiv_rn(w1, scale)), -15.0f), 15.0f);
        float d0 = __fsub_rn(__fmul_rn(q0, scale), w0);
        float d1 = __fsub_rn(__fmul_rn(q1, scale), w1);
        float err = __fadd_rn(__fmul_rn(d0, d0), __fmul_rn(d1, d1));
        #pragma unroll
        for (int o = 16; o; o >>= 1) err = __fadd_rn(err, __shfl_xor_sync(0xffffffffu, err, o));

        if (err < best_err) { best_err = err; best_scale = scale; }
    }

    float q0 = fminf(fmaxf(rintf(__fdiv_rn(w0, best_scale)), -15.0f), 15.0f);
    float q1 = fminf(fmaxf(rintf(__fdiv_rn(w1, best_scale)), -15.0f), 15.0f);
    wq[base + lane]      = __fmul_rn(q0, best_scale);
    wq[base + 32 + lane] = __fmul_rn(q1, best_scale);
}

// ---------------------------------------------------------------------------
// TN SGEMM: C[m,n] = sum_k A[m,k] * B[n,k].  A: MxK row-major, B: NxK row-major.
// 128x128x8 tile, 256 threads, 8x8 microtile, double-buffered smem,
// packed fma.rn.f32x2 inner loop (2 FMA lanes / instruction on sm_100a).
// RELUSQ=1 fuses g = relu(c)^2 into the epilogue (for GEMM1).
// All dims are multiples of the tile sizes here, so no bounds checks.
// ---------------------------------------------------------------------------
template<int RELUSQ>
__global__ void __launch_bounds__(256) sgemm_tn(
    const float* __restrict__ A, const float* __restrict__ B,
    float* __restrict__ C, int M, int N, int K)
{
    __shared__ __align__(16) float As[2][8][128];
    __shared__ __align__(16) float Bs[2][8][128];

    const int tid  = threadIdx.x;
    const int tx   = tid & 15;     // N-direction microtile index
    const int ty   = tid >> 4;     // M-direction microtile index
    const int bm   = blockIdx.y;
    const int bn   = blockIdx.x;
    const int lrow = tid >> 1;         // 0..127: tile row loaded by this thread
    const int lcol = (tid & 1) * 4;    // 0 or 4: k-offset within 8-wide tile

    const float* Ag = A + ((size_t)(bm * 128 + lrow)) * K + lcol;
    const float* Bg = B + ((size_t)(bn * 128 + lrow)) * K + lcol;

    // 8x8 fp32 accumulators as 8x4 packed f32x2 pairs (low = even column)
    unsigned long long acc[8][4];
    #pragma unroll
    for (int i = 0; i < 8; i++)
        #pragma unroll
        for (int j = 0; j < 4; j++) acc[i][j] = 0ull;

    // Preload tile 0
    float4 a4 = *(const float4*)Ag;
    float4 b4 = *(const float4*)Bg;
    As[0][lcol + 0][lrow] = a4.x; As[0][lcol + 1][lrow] = a4.y;
    As[0][lcol + 2][lrow] = a4.z; As[0][lcol + 3][lrow] = a4.w;
    Bs[0][lcol + 0][lrow] = b4.x; Bs[0][lcol + 1][lrow] = b4.y;
    Bs[0][lcol + 2][lrow] = b4.z; Bs[0][lcol + 3][lrow] = b4.w;
    __syncthreads();

    const int nt = K >> 3;
    for (int t = 0; t < nt; t++) {
        const int cur = t & 1;
        if (t + 1 < nt) {
            a4 = *(const float4*)(Ag + (size_t)(t + 1) * 8);
            b4 = *(const float4*)(Bg + (size_t)(t + 1) * 8);
        }
        #pragma unroll
        for (int k = 0; k < 8; k++) {
            float a[8];
            *(float4*)(a)     = *(const float4*)&As[cur][k][ty * 8];
            *(float4*)(a + 4) = *(const float4*)&As[cur][k][ty * 8 + 4];
            unsigned long long b2[4];
            *(ulonglong2*)(b2)     = *(const ulonglong2*)&Bs[cur][k][tx * 8];
            *(ulonglong2*)(b2 + 2) = *(const ulonglong2*)&Bs[cur][k][tx * 8 + 4];
            #pragma unroll
            for (int i = 0; i < 8; i++) {
                unsigned long long av;
                unsigned int au = __float_as_uint(a[i]);
                asm("mov.b64 %0, {%1, %1};" : "=l"(av) : "r"(au));
                #pragma unroll
                for (int j = 0; j < 4; j++) {
                    asm("fma.rn.f32x2 %0, %1, %2, %0;"
                        : "+l"(acc[i][j]) : "l"(av), "l"(b2[j]));
                }
            }
        }
        if (t + 1 < nt) {
            const int nxt = cur ^ 1;
            As[nxt][lcol + 0][lrow] = a4.x; As[nxt][lcol + 1][lrow] = a4.y;
            As[nxt][lcol + 2][lrow] = a4.z; As[nxt][lcol + 3][lrow] = a4.w;
            Bs[nxt][lcol + 0][lrow] = b4.x; Bs[nxt][lcol + 1][lrow] = b4.y;
            Bs[nxt][lcol + 2][lrow] = b4.z; Bs[nxt][lcol + 3][lrow] = b4.w;
            __syncthreads();
        }
    }

    // Epilogue
    const size_t row0 = (size_t)bm * 128 + (size_t)ty * 8;
    const int    col0 = bn * 128 + tx * 8;
    #pragma unroll
    for (int i = 0; i < 8; i++) {
        float v[8];
        #pragma unroll
        for (int j = 0; j < 4; j++) {
            float lo, hi;
            asm("mov.b64 {%0, %1}, %2;" : "=f"(lo), "=f"(hi) : "l"(acc[i][j]));
            v[2 * j]     = lo;
            v[2 * j + 1] = hi;
        }
        if (RELUSQ) {
            #pragma unroll
            for (int j = 0; j < 8; j++) { float r = fmaxf(v[j], 0.0f); v[j] = r * r; }
        }
        float* Cp = C + (row0 + i) * (size_t)N + col0;
        *(float4*)(Cp)     = make_float4(v[0], v[1], v[2], v[3]);
        *(float4*)(Cp + 4) = make_float4(v[4], v[5], v[6], v[7]);
    }
}

// ---------------------------------------------------------------------------
extern "C" void kernel_launch(void* const* d_in, const int* in_sizes, int n_in,
                              void* d_out, int out_size)
{
    const float* x     = (const float*)d_in[0];
    const float* wfc   = (const float*)d_in[1];
    const float* wproj = (const float*)d_in[2];
    float*       out   = (float*)d_out;

    const int M = in_sizes[0] / DIM;   // 8192 tokens

    float *p_wfcq, *p_wprojq, *p_act;
    cudaGetSymbolAddress((void**)&p_wfcq,   g_wfcq);
    cudaGetSymbolAddress((void**)&p_wprojq, g_wprojq);
    cudaGetSymbolAddress((void**)&p_act,    g_act);

    const int nblk = HID * DIM / 64;   // 262144 quant blocks per weight matrix
    quant_kernel<<<(nblk * 32) / 256, 256>>>(wfc,   p_wfcq,   nblk);
    quant_kernel<<<(nblk * 32) / 256, 256>>>(wproj, p_wprojq, nblk);

    // h2 = relu(x @ wfc_q^T)^2   -> g_act   [M, HID]
    sgemm_tn<1><<<dim3(HID / 128, M / 128), 256>>>(x, p_wfcq, p_act, M, HID, DIM);
    // out = h2 @ wproj_q^T                  [M, DIM]
    sgemm_tn<0><<<dim3(DIM / 128, M / 128), 256>>>(p_act, p_wprojq, out, M, DIM, HID);
}

// round 4
// speedup vs baseline: 2.8974x; 2.8974x over previous
#include <cuda_runtime.h>
#include <cuda_bf16.h>
#include <math_constants.h>
#include <cstdint>

#define DIM  2048
#define HID  8192
#define NTOK 8192

// ---------------- scratch (device globals; allocation-free) ----------------
__device__ __nv_bfloat16 g_qfc[(size_t)HID * DIM];      // exact int5 codes as bf16
__device__ float         g_sfc[(DIM / 64) * HID];       // scales [blk][n]
__device__ __nv_bfloat16 g_qpj[(size_t)DIM * HID];
__device__ float         g_spj[(HID / 64) * DIM];
__device__ __nv_bfloat16 g_xh[(size_t)NTOK * DIM];
__device__ __nv_bfloat16 g_xl[(size_t)NTOK * DIM];
__device__ __nv_bfloat16 g_ah[(size_t)NTOK * HID];
__device__ __nv_bfloat16 g_al[(size_t)NTOK * HID];

// ---------------- PTX helpers (sm_80-level only; NO tcgen05) ----------------
__device__ __forceinline__ uint32_t smem_u32(const void* p) {
    uint32_t a;
    asm("{ .reg .u64 t; cvta.to.shared.u64 t, %1; cvt.u32.u64 %0, t; }" : "=r"(a) : "l"(p));
    return a;
}
__device__ __forceinline__ void cp16(uint32_t dst, const void* src) {
    asm volatile("cp.async.cg.shared.global [%0], [%1], 16;" :: "r"(dst), "l"(src));
}
#define CP_COMMIT() asm volatile("cp.async.commit_group;" ::: "memory")
#define CP_WAIT(n)  asm volatile("cp.async.wait_group %0;" :: "n"(n) : "memory")

__device__ __forceinline__ void ldmx4(uint32_t* r, uint32_t a) {
    asm volatile("ldmatrix.sync.aligned.m8n8.x4.shared.b16 {%0,%1,%2,%3}, [%4];"
                 : "=r"(r[0]), "=r"(r[1]), "=r"(r[2]), "=r"(r[3]) : "r"(a));
}
__device__ __forceinline__ void mma16816(float* d, const uint32_t* a, uint32_t b0, uint32_t b1) {
    asm volatile("mma.sync.aligned.m16n8k16.row.col.f32.bf16.bf16.f32 "
                 "{%0,%1,%2,%3}, {%4,%5,%6,%7}, {%8,%9}, {%0,%1,%2,%3};"
                 : "+f"(d[0]), "+f"(d[1]), "+f"(d[2]), "+f"(d[3])
                 : "r"(a[0]), "r"(a[1]), "r"(a[2]), "r"(a[3]), "r"(b0), "r"(b1));
}

// ---------------- quant: blockwise int5 MSE -> exact bf16 codes + fp32 scale ----
// Bit-exact argmin vs jnp reference: IEEE div, rintf (round-half-even), no FMA
// contraction in error terms, SHRINKS per np.linspace in double, strict <.
__global__ void quant_kernel(const float* __restrict__ w,
                             __nv_bfloat16* __restrict__ q_out,
                             float* __restrict__ s_out,
                             int nblk, int nbpr, int nrows)
{
    int gw   = (int)((blockIdx.x * blockDim.x + threadIdx.x) >> 5);
    int lane = threadIdx.x & 31;
    if (gw >= nblk) return;

    size_t base = (size_t)gw * 64;
    float w0 = w[base + lane];
    float w1 = w[base + 32 + lane];

    float am = fmaxf(fabsf(w0), fabsf(w1));
    #pragma unroll
    for (int o = 16; o; o >>= 1) am = fmaxf(am, __shfl_xor_sync(0xffffffffu, am, o));

    float bs = __fdiv_rn(fmaxf(am, 1e-8f), 15.0f);

    float best_err = CUDART_INF_F, best_scale = bs;

    #pragma unroll 1
    for (int i = 0; i < 16; i++) {
        double sd = (i == 15) ? 1.0 : (0.4 + (double)i * (0.6 / 15.0));
        float  s  = (float)sd;
        float scale = __fmul_rn(bs, s);

        float q0 = fminf(fmaxf(rintf(__fdiv_rn(w0, scale)), -15.0f), 15.0f);
        float q1 = fminf(fmaxf(rintf(__fdiv_rn(w1, scale)), -15.0f), 15.0f);
        float d0 = __fsub_rn(__fmul_rn(q0, scale), w0);
        float d1 = __fsub_rn(__fmul_rn(q1, scale), w1);
        float err = __fadd_rn(__fmul_rn(d0, d0), __fmul_rn(d1, d1));
        #pragma unroll
        for (int o = 16; o; o >>= 1) err = __fadd_rn(err, __shfl_xor_sync(0xffffffffu, err, o));
        if (err < best_err) { best_err = err; best_scale = scale; }
    }

    float q0 = fminf(fmaxf(rintf(__fdiv_rn(w0, best_scale)), -15.0f), 15.0f);
    float q1 = fminf(fmaxf(rintf(__fdiv_rn(w1, best_scale)), -15.0f), 15.0f);

    q_out[base + lane]      = __float2bfloat16_rn(q0);   // exact (|q|<=15)
    q_out[base + 32 + lane] = __float2bfloat16_rn(q1);
    if (lane == 0) {
        int n   = gw / nbpr;
        int blk = gw % nbpr;
        s_out[(size_t)blk * nrows + n] = best_scale;
    }
}

// ---------------- split fp32 -> bf16 hi/lo ----------------
__global__ void split_kernel(const float* __restrict__ x,
                             __nv_bfloat16* __restrict__ xh,
                             __nv_bfloat16* __restrict__ xl)
{
    size_t i = ((size_t)blockIdx.x * blockDim.x + threadIdx.x) * 4;
    float4 v = *(const float4*)(x + i);
    float f[4] = {v.x, v.y, v.z, v.w};
    ushort hh[4], ll[4];
    #pragma unroll
    for (int j = 0; j < 4; j++) {
        __nv_bfloat16 h = __float2bfloat16_rn(f[j]);
        __nv_bfloat16 l = __float2bfloat16_rn(f[j] - __bfloat162float(h));
        hh[j] = __bfloat16_as_ushort(h);
        ll[j] = __bfloat16_as_ushort(l);
    }
    *(uint2*)(xh + i) = *(uint2*)hh;
    *(uint2*)(xl + i) = *(uint2*)ll;
}

// ---------------- HMMA split-bf16 GEMM with per-block weight scales ----------
// C[m,n] = sum_blk scale[blk][n] * sum_{k in blk} (Ah[m,k]+Al[m,k]) * q[n,k]
// Tile 128x128x64; 8 warps as 2(M)x4(N); warp tile 64x32 = 4 m16 x 4 n8.
// All products exact in bf16 (q has <=4-bit mantissa); only the A split rounds.
#define ROWB   144                    // 64 bf16 row + 16B pad (conflict-free)
#define ATILE  (128 * ROWB)           // 18432
#define OFF_AH 0
#define OFF_AL ATILE
#define OFF_QB (2 * ATILE)
#define STAGE  (3 * ATILE)            // 55296
#define SMEM_TOT (2 * STAGE)          // 110592

template<int RELUSQ>
__global__ void __launch_bounds__(256) gemm_hmma(
    const __nv_bfloat16* __restrict__ Ahp, const __nv_bfloat16* __restrict__ Alp,
    const __nv_bfloat16* __restrict__ Qp,  const float* __restrict__ Sp,
    float* __restrict__ Cf,
    __nv_bfloat16* __restrict__ Ch, __nv_bfloat16* __restrict__ Cl,
    int N, int K)
{
    extern __shared__ char smem[];
    const uint32_t sb = smem_u32(smem);
    const int tid  = threadIdx.x;
    const int lane = tid & 31;
    const int wid  = tid >> 5;
    const int wm   = wid >> 2;          // 0..1  (64 rows each)
    const int wn   = wid & 3;           // 0..3  (32 cols each)
    const int bm   = blockIdx.y, bn = blockIdx.x;

    // per-thread gmem load mapping: 4 chunks per array per thread
    const int lrow = tid >> 3;          // 0..31 (+32 per i)
    const int lkc  = (tid & 7) * 16;    // byte offset in 128B row
    const char* pAh = (const char*)(Ahp + (size_t)(bm * 128) * K);
    const char* pAl = (const char*)(Alp + (size_t)(bm * 128) * K);
    const char* pQ  = (const char*)(Qp  + (size_t)(bn * 128) * K);
    const size_t rowbytes = (size_t)K * 2;

    auto load_stage = [&](int buf, int kt) {
        const uint32_t s0 = sb + buf * STAGE;
        const size_t kofs = (size_t)kt * 128;
        #pragma unroll
        for (int i = 0; i < 4; i++) {
            const int r = lrow + i * 32;
            const uint32_t so = (uint32_t)(r * ROWB + lkc);
            const size_t go = (size_t)r * rowbytes + kofs + lkc;
            cp16(s0 + OFF_AH + so, pAh + go);
            cp16(s0 + OFF_AL + so, pAl + go);
            cp16(s0 + OFF_QB + so, pQ  + go);
        }
        CP_COMMIT();
    };

    // ldmatrix per-lane addressing: 4 8x8 tiles = (row 0-7 / 8-15) x (k 0-7 / 8-15)
    const int mrow = (lane & 7) + ((lane >> 3) & 1) * 8;   // row within 16-row tile
    const int mcol = (lane >> 4) * 16;                     // 0 or 16 bytes (k half)

    float cm[4][4][4];
    #pragma unroll
    for (int a = 0; a < 4; a++)
        #pragma unroll
        for (int b = 0; b < 4; b++)
            #pragma unroll
            for (int c = 0; c < 4; c++) cm[a][b][c] = 0.0f;

    const int nt = K >> 6;
    load_stage(0, 0);
    load_stage(1, 1);

    for (int t = 0; t < nt; t++) {
        const int cur = t & 1;
        if (t + 1 < nt) { CP_WAIT(1); } else { CP_WAIT(0); }
        __syncthreads();

        const uint32_t base = sb + cur * STAGE;
        const uint32_t aAh = base + OFF_AH + (wm * 64 + mrow) * ROWB + mcol;
        const uint32_t aAl = base + OFF_AL + (wm * 64 + mrow) * ROWB + mcol;
        const uint32_t aQ  = base + OFF_QB + (wn * 32 + mrow) * ROWB + mcol;

        float cb[4][4][4];
        #pragma unroll
        for (int a = 0; a < 4; a++)
            #pragma unroll
            for (int b = 0; b < 4; b++)
                #pragma unroll
                for (int c = 0; c < 4; c++) cb[a][b][c] = 0.0f;

        #pragma unroll
        for (int ks = 0; ks < 4; ks++) {
            uint32_t bq[2][4];
            ldmx4(bq[0], aQ + ks * 32);
            ldmx4(bq[1], aQ + 16 * ROWB + ks * 32);

            uint32_t fa[4][4];
            #pragma unroll
            for (int mt = 0; mt < 4; mt++) ldmx4(fa[mt], aAh + mt * 16 * ROWB + ks * 32);
            #pragma unroll
            for (int mt = 0; mt < 4; mt++)
                #pragma unroll
                for (int ntile = 0; ntile < 4; ntile++)
                    mma16816(cb[mt][ntile], fa[mt],
                             bq[ntile >> 1][ntile & 1], bq[ntile >> 1][2 + (ntile & 1)]);

            #pragma unroll
            for (int mt = 0; mt < 4; mt++) ldmx4(fa[mt], aAl + mt * 16 * ROWB + ks * 32);
            #pragma unroll
            for (int mt = 0; mt < 4; mt++)
                #pragma unroll
                for (int ntile = 0; ntile < 4; ntile++)
                    mma16816(cb[mt][ntile], fa[mt],
                             bq[ntile >> 1][ntile & 1], bq[ntile >> 1][2 + (ntile & 1)]);
        }

        // fold per-block weight scale into the main accumulators
        const float* sp = Sp + (size_t)t * N + bn * 128 + wn * 32 + 2 * (lane & 3);
        #pragma unroll
        for (int ntile = 0; ntile < 4; ntile++) {
            const float2 s2 = *(const float2*)(sp + ntile * 8);
            #pragma unroll
            for (int mt = 0; mt < 4; mt++) {
                cm[mt][ntile][0] += cb[mt][ntile][0] * s2.x;
                cm[mt][ntile][1] += cb[mt][ntile][1] * s2.y;
                cm[mt][ntile][2] += cb[mt][ntile][2] * s2.x;
                cm[mt][ntile][3] += cb[mt][ntile][3] * s2.y;
            }
        }

        __syncthreads();
        if (t + 2 < nt) load_stage(cur, t + 2);
    }

    // ---------------- epilogue ----------------
    const int g  = lane >> 2;
    const int t4 = lane & 3;
    #pragma unroll
    for (int mt = 0; mt < 4; mt++) {
        const int row = bm * 128 + wm * 64 + mt * 16 + g;
        #pragma unroll
        for (int ntile = 0; ntile < 4; ntile++) {
            const int col = bn * 128 + wn * 32 + ntile * 8 + 2 * t4;
            float v0 = cm[mt][ntile][0], v1 = cm[mt][ntile][1];
            float v2 = cm[mt][ntile][2], v3 = cm[mt][ntile][3];
            if (RELUSQ) {
                float r0 = fmaxf(v0, 0.0f); r0 *= r0;
                float r1 = fmaxf(v1, 0.0f); r1 *= r1;
                float r2 = fmaxf(v2, 0.0f); r2 *= r2;
                float r3 = fmaxf(v3, 0.0f); r3 *= r3;
                __nv_bfloat16 h0 = __float2bfloat16_rn(r0), h1 = __float2bfloat16_rn(r1);
                __nv_bfloat16 h2 = __float2bfloat16_rn(r2), h3 = __float2bfloat16_rn(r3);
                uint32_t lo01 = ((uint32_t)__bfloat16_as_ushort(__float2bfloat16_rn(r1 - __bfloat162float(h1))) << 16)
                              |  __bfloat16_as_ushort(__float2bfloat16_rn(r0 - __bfloat162float(h0)));
                uint32_t lo23 = ((uint32_t)__bfloat16_as_ushort(__float2bfloat16_rn(r3 - __bfloat162float(h3))) << 16)
                              |  __bfloat16_as_ushort(__float2bfloat16_rn(r2 - __bfloat162float(h2)));
                uint32_t hi01 = ((uint32_t)__bfloat16_as_ushort(h1) << 16) | __bfloat16_as_ushort(h0);
                uint32_t hi23 = ((uint32_t)__bfloat16_as_ushort(h3) << 16) | __bfloat16_as_ushort(h2);
                *(uint32_t*)((char*)Ch + ((size_t)row * N + col) * 2)       = hi01;
                *(uint32_t*)((char*)Cl + ((size_t)row * N + col) * 2)       = lo01;
                *(uint32_t*)((char*)Ch + ((size_t)(row + 8) * N + col) * 2) = hi23;
                *(uint32_t*)((char*)Cl + ((size_t)(row + 8) * N + col) * 2) = lo23;
            } else {
                *(float2*)(Cf + (size_t)row * N + col)       = make_float2(v0, v1);
                *(float2*)(Cf + (size_t)(row + 8) * N + col) = make_float2(v2, v3);
            }
        }
    }
}

// ---------------------------------------------------------------------------
extern "C" void kernel_launch(void* const* d_in, const int* in_sizes, int n_in,
                              void* d_out, int out_size)
{
    const float* x     = (const float*)d_in[0];
    const float* wfc   = (const float*)d_in[1];
    const float* wproj = (const float*)d_in[2];
    float*       out   = (float*)d_out;

    const int M = in_sizes[0] / DIM;     // 8192 tokens

    __nv_bfloat16 *qfc, *qpj, *xh, *xl, *ah, *al;
    float *sfc, *spj;
    cudaGetSymbolAddress((void**)&qfc, g_qfc);
    cudaGetSymbolAddress((void**)&sfc, g_sfc);
    cudaGetSymbolAddress((void**)&qpj, g_qpj);
    cudaGetSymbolAddress((void**)&spj, g_spj);
    cudaGetSymbolAddress((void**)&xh,  g_xh);
    cudaGetSymbolAddress((void**)&xl,  g_xl);
    cudaGetSymbolAddress((void**)&ah,  g_ah);
    cudaGetSymbolAddress((void**)&al,  g_al);

    cudaFuncSetAttribute(gemm_hmma<1>, cudaFuncAttributeMaxDynamicSharedMemorySize, SMEM_TOT);
    cudaFuncSetAttribute(gemm_hmma<0>, cudaFuncAttributeMaxDynamicSharedMemorySize, SMEM_TOT);

    // quantize: w_fc [HID, DIM] (32 blocks/row), w_proj [DIM, HID] (128 blocks/row)
    const int nblk1 = HID * DIM / 64;
    quant_kernel<<<(nblk1 * 32) / 256, 256>>>(wfc,   qfc, sfc, nblk1, DIM / 64, HID);
    quant_kernel<<<(nblk1 * 32) / 256, 256>>>(wproj, qpj, spj, nblk1, HID / 64, DIM);
    split_kernel<<<(M * DIM / 4) / 256, 256>>>(x, xh, xl);

    // GEMM1: act = split(relu(x @ wfc_dq^T)^2) -> (ah, al)   [M, HID]
    gemm_hmma<1><<<dim3(HID / 128, M / 128), 256, SMEM_TOT>>>(
        xh, xl, qfc, sfc, nullptr, ah, al, HID, DIM);
    // GEMM2: out = act @ wproj_dq^T   [M, DIM] fp32
    gemm_hmma<0><<<dim3(DIM / 128, M / 128), 256, SMEM_TOT>>>(
        ah, al, qpj, spj, out, nullptr, nullptr, DIM, HID);
}